// round 4
// baseline (speedup 1.0000x reference)
#include <cuda_runtime.h>
#include <cstdint>

#define S 64
#define D 128
#define ALPHA 0.2f
#define THREADS 512
#define NWARP 16
#define NSTAGE 3
#define GROUP_BYTES 32768                 // S*D*4
#define STAGE_BYTES (2 * GROUP_BYTES)     // c tile + v tile
#define SMEM_DYN (1024 + NSTAGE * STAGE_BYTES)

__device__ __forceinline__ uint32_t smem_u32(const void* p) {
    return (uint32_t)__cvta_generic_to_shared(p);
}

#define MBAR_INIT(addr, count) \
    asm volatile("mbarrier.init.shared.b64 [%0], %1;" :: "r"(addr), "r"(count) : "memory")

#define MBAR_EXPECT_TX(addr, bytes) \
    asm volatile("mbarrier.arrive.expect_tx.shared.b64 _, [%0], %1;" :: "r"(addr), "r"(bytes) : "memory")

#define BULK_G2S(dst, src, bytes, mbar) \
    asm volatile("cp.async.bulk.shared::cta.global.mbarrier::complete_tx::bytes [%0], [%1], %2, [%3];" \
                 :: "r"(dst), "l"(src), "r"(bytes), "r"(mbar) : "memory")

#define FENCE_PROXY_ASYNC() asm volatile("fence.proxy.async.shared::cta;" ::: "memory")

#define MBAR_WAIT(addr, parity) do {                                                  \
    asm volatile("{\n\t.reg .pred P;\n\tWAIT_%=:\n\t"                                 \
                 "mbarrier.try_wait.parity.shared.b64 P, [%0], %1;\n\t"               \
                 "@!P bra WAIT_%=;\n\t}"                                              \
                 :: "r"(addr), "r"(parity) : "memory");                               \
} while (0)

__global__ void __launch_bounds__(THREADS, 1)
gat_kernel(const float* __restrict__ center,
           const float* __restrict__ nbr,
           const float* __restrict__ a,
           float* __restrict__ out,
           int ngroups)
{
    extern __shared__ char smem[];
    __shared__ float s_m[NWARP];
    __shared__ float s_sum[NWARP];
    __shared__ float s_acc[NWARP][D];

    const uint32_t sbase = smem_u32(smem);
    const uint32_t mbar0 = sbase;             // full[s] at +8*s
    const uint32_t tile0 = sbase + 1024;

    const int tid  = threadIdx.x;
    const int warp = tid >> 5;
    const int lane = tid & 31;

    const int bid  = blockIdx.x;
    const int gdim = gridDim.x;
    const int mycount = (ngroups - bid + gdim - 1) / gdim;   // groups: bid + it*gdim

    if (tid == 0)
        for (int s = 0; s < NSTAGE; s++) MBAR_INIT(mbar0 + 8 * s, 1);
    __syncthreads();

    // a[0:128] with center, a[128:256] with nbr; one float4 slice per lane.
    const float4 a1 = reinterpret_cast<const float4*>(a)[lane];
    const float4 a2 = reinterpret_cast<const float4*>(a)[32 + lane];

    // ---- Prologue: fill the pipeline. ----
    if (tid == 0) {
        #pragma unroll
        for (int i = 0; i < NSTAGE; i++) {
            if (i < mycount) {
                const size_t g = (size_t)bid + (size_t)i * gdim;
                const uint32_t dst = tile0 + i * STAGE_BYTES;
                const uint32_t bar = mbar0 + 8 * i;
                MBAR_EXPECT_TX(bar, STAGE_BYTES);
                BULK_G2S(dst,               (const char*)center + g * GROUP_BYTES, GROUP_BYTES, bar);
                BULK_G2S(dst + GROUP_BYTES, (const char*)nbr    + g * GROUP_BYTES, GROUP_BYTES, bar);
            }
        }
    }

    for (int it = 0; it < mycount; it++) {
        const int s  = it % NSTAGE;
        const int ph = (it / NSTAGE) & 1;
        const size_t g = (size_t)bid + (size_t)it * gdim;

        MBAR_WAIT(mbar0 + 8 * s, ph);

        // ---- Compute from smem: warp handles 4 rows. ----
        const float4* cs = reinterpret_cast<const float4*>(smem + 1024 + (size_t)s * STAGE_BYTES);
        const float4* vs = cs + (GROUP_BYTES / 16);

        float4 v[4];
        float  d[4];
        #pragma unroll
        for (int i = 0; i < 4; i++) {
            const int row = warp * 4 + i;
            const float4 c = cs[row * 32 + lane];
            v[i]           = vs[row * 32 + lane];
            d[i] = c.x * a1.x + c.y * a1.y + c.z * a1.z + c.w * a1.w
                 + v[i].x * a2.x + v[i].y * a2.y + v[i].z * a2.z + v[i].w * a2.w;
        }
        #pragma unroll
        for (int i = 0; i < 4; i++) {
            #pragma unroll
            for (int off = 16; off; off >>= 1)
                d[i] += __shfl_xor_sync(0xffffffffu, d[i], off);
        }

        float m = -1e30f;
        #pragma unroll
        for (int i = 0; i < 4; i++) {
            d[i] = (d[i] > 0.f) ? d[i] : ALPHA * d[i];
            m = fmaxf(m, d[i]);
        }
        float sm = 0.f;
        float4 acc = make_float4(0.f, 0.f, 0.f, 0.f);
        #pragma unroll
        for (int i = 0; i < 4; i++) {
            const float p = __expf(d[i] - m);
            sm += p;
            acc.x += p * v[i].x;
            acc.y += p * v[i].y;
            acc.z += p * v[i].z;
            acc.w += p * v[i].w;
        }
        if (lane == 0) { s_m[warp] = m; s_sum[warp] = sm; }
        reinterpret_cast<float4*>(s_acc[warp])[lane] = acc;

        __syncthreads();   // stage s consumed; s_acc ready

        // ---- Refill stage s for group g + NSTAGE*gdim (overlaps epilogue). ----
        if (tid == 0) {
            const int nx = it + NSTAGE;
            if (nx < mycount) {
                const size_t gn = (size_t)bid + (size_t)nx * gdim;
                const uint32_t dst = tile0 + s * STAGE_BYTES;
                const uint32_t bar = mbar0 + 8 * s;
                FENCE_PROXY_ASYNC();
                MBAR_EXPECT_TX(bar, STAGE_BYTES);
                BULK_G2S(dst,               (const char*)center + gn * GROUP_BYTES, GROUP_BYTES, bar);
                BULK_G2S(dst + GROUP_BYTES, (const char*)nbr    + gn * GROUP_BYTES, GROUP_BYTES, bar);
            }
        }

        // ---- Cross-warp combine; 128 threads, one feature each. ----
        if (tid < D) {
            float M = s_m[0];
            #pragma unroll
            for (int w = 1; w < NWARP; w++) M = fmaxf(M, s_m[w]);
            float tot = 0.f, o = 0.f;
            #pragma unroll
            for (int w = 0; w < NWARP; w++) {
                const float f = __expf(s_m[w] - M);
                tot += s_sum[w] * f;
                o   += s_acc[w][tid] * f;
            }
            out[g * D + tid] = o * __frcp_rn(tot);
        }
        __syncthreads();   // protect s_m/s_sum/s_acc for next iteration
    }
}

extern "C" void kernel_launch(void* const* d_in, const int* in_sizes, int n_in,
                              void* d_out, int out_size)
{
    const float* center = (const float*)d_in[0];
    const float* nbr    = (const float*)d_in[1];
    const float* a      = (const float*)d_in[2];
    float* out          = (float*)d_out;

    const int ngroups = in_sizes[0] / (S * D);   // 8192

    int dev = 0, sms = 148;
    cudaGetDevice(&dev);
    cudaDeviceGetAttribute(&sms, cudaDevAttrMultiProcessorCount, dev);

    cudaFuncSetAttribute(gat_kernel, cudaFuncAttributeMaxDynamicSharedMemorySize, SMEM_DYN);
    gat_kernel<<<sms, THREADS, SMEM_DYN>>>(center, nbr, a, out, ngroups);
}

// round 8
// speedup vs baseline: 1.0616x; 1.0616x over previous
#include <cuda_runtime.h>

#define S 64
#define D 128
#define ALPHA 0.2f
#define NWARP 8

__global__ void __launch_bounds__(256, 4)
gat_kernel(const float* __restrict__ center,
           const float* __restrict__ nbr,
           const float* __restrict__ a,
           float* __restrict__ out,
           int ngroups)
{
    __shared__ float s_m[NWARP];
    __shared__ float s_sum[NWARP];
    __shared__ float s_acc[NWARP][D];   // 4 KB

    const int tid  = threadIdx.x;
    const int warp = tid >> 5;
    const int lane = tid & 31;

    // a[0:128] pairs with center, a[128:256] with nbr (loop-invariant).
    const float4 a1 = reinterpret_cast<const float4*>(a)[lane];
    const float4 a2 = reinterpret_cast<const float4*>(a)[32 + lane];

    const int stride = gridDim.x;

    for (int g = blockIdx.x; g < ngroups; g += stride) {
        const float4* __restrict__ cvec =
            reinterpret_cast<const float4*>(center) + (size_t)g * (S * D / 4) + warp * 8 * 32;
        const float4* __restrict__ nvec =
            reinterpret_cast<const float4*>(nbr)    + (size_t)g * (S * D / 4) + warp * 8 * 32;

        // ---- Phase 1: burst-load 8 c rows + 8 v rows; partial dots per lane.
        //      Issues immediately after previous iteration's epilogue — no
        //      barrier between epilogue and these loads.
        float4 v[8];
        float  d[8];
        #pragma unroll
        for (int i = 0; i < 8; i++) {
            const float4 c = __ldcs(&cvec[i * 32 + lane]);
            v[i]           = __ldcs(&nvec[i * 32 + lane]);
            d[i] = c.x * a1.x + c.y * a1.y + c.z * a1.z + c.w * a1.w
                 + v[i].x * a2.x + v[i].y * a2.y + v[i].z * a2.z + v[i].w * a2.w;
        }

        // ---- Phase 2: butterfly-reduce all 8 dots (off the load path). ----
        #pragma unroll
        for (int i = 0; i < 8; i++) {
            #pragma unroll
            for (int off = 16; off; off >>= 1)
                d[i] += __shfl_xor_sync(0xffffffffu, d[i], off);
        }

        // ---- Phase 3: per-warp softmax over 8 logits + weighted accumulate.
        float m = -1e30f;
        #pragma unroll
        for (int i = 0; i < 8; i++) {
            d[i] = (d[i] > 0.f) ? d[i] : ALPHA * d[i];   // leaky relu
            m = fmaxf(m, d[i]);
        }
        float sm = 0.f;
        float4 acc = make_float4(0.f, 0.f, 0.f, 0.f);
        #pragma unroll
        for (int i = 0; i < 8; i++) {
            const float p = __expf(d[i] - m);
            sm += p;
            acc.x += p * v[i].x;
            acc.y += p * v[i].y;
            acc.z += p * v[i].z;
            acc.w += p * v[i].w;
        }

        __syncthreads();   // previous iteration's epilogue has consumed s_acc

        if (lane == 0) { s_m[warp] = m; s_sum[warp] = sm; }
        reinterpret_cast<float4*>(s_acc[warp])[lane] = acc;
        __syncthreads();

        // ---- Phase 4: cross-warp combine; 128 threads, one feature each. ----
        if (tid < D) {
            float M = s_m[0];
            #pragma unroll
            for (int w = 1; w < NWARP; w++) M = fmaxf(M, s_m[w]);

            float tot = 0.f, o = 0.f;
            #pragma unroll
            for (int w = 0; w < NWARP; w++) {
                const float f = __expf(s_m[w] - M);
                tot += s_sum[w] * f;
                o   += s_acc[w][tid] * f;
            }
            out[(size_t)g * D + tid] = o * __frcp_rn(tot);
        }
        // no trailing barrier: next iteration's loads don't touch smem, and
        // the leading barrier protects s_acc before it is rewritten.
    }
}

extern "C" void kernel_launch(void* const* d_in, const int* in_sizes, int n_in,
                              void* d_out, int out_size)
{
    const float* center = (const float*)d_in[0];
    const float* nbr    = (const float*)d_in[1];
    const float* a      = (const float*)d_in[2];
    float* out          = (float*)d_out;

    const int ngroups = in_sizes[0] / (S * D);   // 8192

    int dev = 0, sms = 148;
    cudaGetDevice(&dev);
    cudaDeviceGetAttribute(&sms, cudaDevAttrMultiProcessorCount, dev);

    gat_kernel<<<4 * sms, 256>>>(center, nbr, a, out, ngroups);
}